// round 13
// baseline (speedup 1.0000x reference)
#include <cuda_runtime.h>
#include <math.h>

#define BB 32
#define CC 64
#define HH 128
#define WW 128
#define QD 8
#define NEGV (-1e4f)

// scratch
__device__ float g_Qt[BB*HH*WW*QD];   // [b,h,w,q] 16.8 MB
__device__ float g_Kt[BB*HH*WW*QD];   // [b,h,w,q] 16.8 MB
__device__ float g_GW[BB*HH*CC*QD];   // [b,h,e,q] 8.4 MB
__device__ float g_sW[BB*HH*QD];
__device__ float g_sH[BB*WW*QD];
__device__ float g_T1[(size_t)BB*HH*WW*CC];  // [b,h,w,e] 134 MB: sum_q GH*Q

__device__ __forceinline__ float softplus_f(float v) {
    return fmaxf(v, 0.f) + log1pf(expf(-fabsf(v)));
}
__device__ __forceinline__ unsigned long long pk2(float lo, float hi) {
    unsigned long long r;
    asm("mov.b64 %0, {%1, %2};" : "=l"(r) : "f"(lo), "f"(hi));
    return r;
}
__device__ __forceinline__ float2 upk2(unsigned long long v) {
    float2 r;
    asm("mov.b64 {%0, %1}, %2;" : "=f"(r.x), "=f"(r.y) : "l"(v));
    return r;
}
#define FMA2(d, a, b, c) \
    asm("fma.rn.f32x2 %0, %1, %2, %3;" : "=l"(d) : "l"(a), "l"(b), "l"(c))

// ---------------------------------------------------------------------------
// P1: per (b,h). Q,K projections (softplus) + GW[e,q] = sum_w x[e,w]K[q,w],
// sW[q] = sum_w K[q,w]. Writes Qt/Kt channels-last.  (unchanged)
// ---------------------------------------------------------------------------
#define S1_FLOATS 10544

__global__ __launch_bounds__(256) void cc_p1_kernel(
    const float* __restrict__ x,
    const float* __restrict__ wq, const float* __restrict__ bq,
    const float* __restrict__ wk, const float* __restrict__ bk)
{
    extern __shared__ float sm[];
    float* XS  = sm;
    float* WQT = sm + 8448;   // [c*8+o]
    float* WKT = sm + 8960;
    float* BQS = sm + 9472;
    float* BKS = sm + 9480;
    float* KS  = sm + 9488;   // [q*132+w]

    const int b = blockIdx.y, h = blockIdx.x, tid = threadIdx.x;

    const float* xrow = x + ((size_t)(b*CC)*HH + h)*WW;
    for (int i = tid; i < CC*WW; i += 256) {
        int c = i >> 7, w = i & 127;
        XS[c*132 + w] = xrow[(size_t)c*HH*WW + w];
    }
    for (int i = tid; i < 512; i += 256) {
        int c = i >> 3, o = i & 7;
        WQT[i] = wq[o*CC + c];
        WKT[i] = wk[o*CC + c];
    }
    if (tid < 8) { BQS[tid] = bq[tid]; BKS[tid] = bk[tid]; }
    __syncthreads();

    {
        const int w = tid & 127, half = tid >> 7;
        const float* WT = half ? WKT : WQT;
        const float* BT = half ? BKS : BQS;
        float acc[8];
        #pragma unroll
        for (int o = 0; o < 8; o++) acc[o] = BT[o];
        #pragma unroll 4
        for (int c = 0; c < CC; c++) {
            float xv  = XS[c*132 + w];
            float4 wa = *(const float4*)&WT[c*8];
            float4 wb = *(const float4*)&WT[c*8 + 4];
            acc[0] = fmaf(wa.x, xv, acc[0]); acc[1] = fmaf(wa.y, xv, acc[1]);
            acc[2] = fmaf(wa.z, xv, acc[2]); acc[3] = fmaf(wa.w, xv, acc[3]);
            acc[4] = fmaf(wb.x, xv, acc[4]); acc[5] = fmaf(wb.y, xv, acc[5]);
            acc[6] = fmaf(wb.z, xv, acc[6]); acc[7] = fmaf(wb.w, xv, acc[7]);
        }
        #pragma unroll
        for (int o = 0; o < 8; o++) acc[o] = softplus_f(acc[o]);
        float* dst = (half ? g_Kt : g_Qt) + ((size_t)(b*HH + h)*WW + w)*QD;
        *(float4*)dst       = make_float4(acc[0], acc[1], acc[2], acc[3]);
        *(float4*)(dst + 4) = make_float4(acc[4], acc[5], acc[6], acc[7]);
        if (half) {
            #pragma unroll
            for (int o = 0; o < 8; o++) KS[o*132 + w] = acc[o];
        }
    }
    __syncthreads();

    {
        const int e = tid >> 2, q0 = tid & 3, q1 = q0 + 4;
        float a0 = 0.f, a1 = 0.f;
        #pragma unroll 8
        for (int ww = 0; ww < WW; ww += 4) {
            float4 xv = *(const float4*)&XS[e*132 + ww];
            float4 k0 = *(const float4*)&KS[q0*132 + ww];
            float4 k1 = *(const float4*)&KS[q1*132 + ww];
            a0 = fmaf(xv.x,k0.x, fmaf(xv.y,k0.y, fmaf(xv.z,k0.z, fmaf(xv.w,k0.w, a0))));
            a1 = fmaf(xv.x,k1.x, fmaf(xv.y,k1.y, fmaf(xv.z,k1.z, fmaf(xv.w,k1.w, a1))));
        }
        float* gw = g_GW + ((size_t)(b*HH + h)*CC + e)*QD;
        gw[q0] = a0;
        gw[q1] = a1;
    }
    if (tid < 8) {
        float s = 0.f;
        for (int ww = 0; ww < WW; ww++) s += KS[tid*132 + ww];
        g_sW[(b*HH + h)*QD + tid] = s;
    }
}

// ---------------------------------------------------------------------------
// P2: per (b, 8-wide w tile).
//   GH[e,q;w] = sum_k x[e,k,w]K[q,k,w]  (full 64 e, in registers)
//   sH[q;w]   = sum_k K[q,k,w]
//   T1[e,h;w] = sum_q GH[e,q;w]*Q[q,h,w]   -> g_T1[b,h,w,e]  (coalesced)
// smem: XS2@0:8192 ([e*128+kk*8+w])  KS2@8192:1024 ([kk*64+q*8+w])
//       GHS@9216:4096 ([w*512+q*64+e])  QS3@13312:8192 ([h*64+w*8+q])
//   -> 21504 floats = 86016 B
// ---------------------------------------------------------------------------
#define S2_FLOATS 21504

__global__ __launch_bounds__(256, 2) void cc_p2_kernel(const float* __restrict__ x)
{
    extern __shared__ float sm[];
    float* XS2 = sm;
    float* KS2 = sm + 8192;
    float* GHS = sm + 9216;
    float* QS3 = sm + 13312;

    const int b = blockIdx.y, wt0 = blockIdx.x * 8, tid = threadIdx.x;
    const int eg = tid >> 5, wl = (tid >> 2) & 7, qp = tid & 3;

    // Q tile for the whole column stripe: QS3[h*64 + w*8 + q]
    {
        const float* qsrc = g_Qt + ((size_t)(b*HH)*WW + wt0)*QD;
        for (int i = tid; i < 2048; i += 256) {
            int hh = i >> 4, j = i & 15;
            *(float4*)&QS3[hh*64 + j*4] =
                *(const float4*)&qsrc[(size_t)hh*WW*QD + j*4];
        }
    }

    float acc0[8], acc1[8];
    #pragma unroll
    for (int i = 0; i < 8; i++) { acc0[i] = 0.f; acc1[i] = 0.f; }
    float sa0 = 0.f, sa1 = 0.f;

    for (int k0 = 0; k0 < HH; k0 += 16) {
        for (int i = tid; i < 2048; i += 256) {     // XS2 fill (float4 units)
            int e = i >> 5, kk = (i >> 1) & 15, j = i & 1;
            *(float4*)&XS2[e*128 + kk*8 + j*4] =
                *(const float4*)(x + ((size_t)(b*CC + e)*HH + k0 + kk)*WW + wt0 + j*4);
        }
        for (int i = tid; i < 1024; i += 256) {     // KS2 fill
            int kk = i >> 6, ww = (i >> 3) & 7, q = i & 7;
            KS2[kk*64 + q*8 + ww] =
                g_Kt[((size_t)(b*HH + k0 + kk)*WW + wt0 + ww)*QD + q];
        }
        __syncthreads();
        #pragma unroll
        for (int kk = 0; kk < 16; kk++) {
            float kv0 = KS2[kk*64 + qp*8 + wl];
            float kv1 = KS2[kk*64 + (qp+4)*8 + wl];
            sa0 += kv0; sa1 += kv1;
            #pragma unroll
            for (int e2 = 0; e2 < 8; e2++) {
                float xv = XS2[(eg*8 + e2)*128 + kk*8 + wl];
                acc0[e2] = fmaf(xv, kv0, acc0[e2]);
                acc1[e2] = fmaf(xv, kv1, acc1[e2]);
            }
        }
        __syncthreads();
    }
    // GH -> smem
    #pragma unroll
    for (int e2 = 0; e2 < 8; e2++) {
        GHS[wl*512 + qp*64     + eg*8 + e2] = acc0[e2];
        GHS[wl*512 + (qp+4)*64 + eg*8 + e2] = acc1[e2];
    }
    if (eg == 0) {
        g_sH[(b*WW + wt0 + wl)*QD + qp]     = sa0;
        g_sH[(b*WW + wt0 + wl)*QD + qp + 4] = sa1;
    }
    __syncthreads();

    // T1 GEMM: thread = (w = tid>>5, e pair = 2*lane, 2*lane+1), loop h
    {
        const int w = tid >> 5, lane = tid & 31, e0 = lane * 2;
        float gh0[8], gh1[8];
        #pragma unroll
        for (int q = 0; q < 8; q++) {
            float2 g2 = *(const float2*)&GHS[w*512 + q*64 + e0];
            gh0[q] = g2.x; gh1[q] = g2.y;
        }
        float* t1dst = g_T1 + ((size_t)(b*HH)*WW + wt0 + w)*CC + e0;
        #pragma unroll 4
        for (int h = 0; h < HH; h++) {
            float4 qa = *(const float4*)&QS3[h*64 + w*8];
            float4 qb = *(const float4*)&QS3[h*64 + w*8 + 4];
            float t0, t1;
            t0 = qa.x*gh0[0]; t1 = qa.x*gh1[0];
            t0 = fmaf(qa.y, gh0[1], t0); t1 = fmaf(qa.y, gh1[1], t1);
            t0 = fmaf(qa.z, gh0[2], t0); t1 = fmaf(qa.z, gh1[2], t1);
            t0 = fmaf(qa.w, gh0[3], t0); t1 = fmaf(qa.w, gh1[3], t1);
            t0 = fmaf(qb.x, gh0[4], t0); t1 = fmaf(qb.x, gh1[4], t1);
            t0 = fmaf(qb.y, gh0[5], t0); t1 = fmaf(qb.y, gh1[5], t1);
            t0 = fmaf(qb.z, gh0[6], t0); t1 = fmaf(qb.z, gh1[6], t1);
            t0 = fmaf(qb.w, gh0[7], t0); t1 = fmaf(qb.w, gh1[7], t1);
            *(float2*)(t1dst + (size_t)h*WW*CC) = make_float2(t0, t1);
        }
    }
}

// ---------------------------------------------------------------------------
// P3: per (b,h).
//  Phase A: T[e,w] = T1[b,h,w,e] + sum_q Q[q,w]*GW[e,q;b,h] + NEG*x[e,w]
//  Phase B: out[c,w] = gamma*( sum_e wvT[e][c]*T[e,w] + bv[c]*S[w] ) + x[c,w]
// smem: XS@0:8448  TS@8448:8448  WVS@16896:4096  BVS@20992:64
//       QS2@21056:1024  SS@22080:128   -> 22208 floats = 88832 B
// ---------------------------------------------------------------------------
#define S3_FLOATS 22208

__global__ __launch_bounds__(256, 2) void cc_p3_kernel(
    const float* __restrict__ x,
    const float* __restrict__ wv, const float* __restrict__ bv,
    const float* __restrict__ gamma, float* __restrict__ out)
{
    extern __shared__ float sm[];
    float* XS  = sm;            // [e*132+w]
    float* TS  = sm + 8448;     // [e*132+w]
    float* WVS = sm + 16896;    // wv transposed: [e*64+o]
    float* BVS = sm + 20992;
    float* QS2 = sm + 21056;    // [w*8+q]
    float* SS  = sm + 22080;

    const int b = blockIdx.y, h = blockIdx.x, tid = threadIdx.x;

    const float* xrow = x + ((size_t)(b*CC)*HH + h)*WW;
    for (int i = tid; i < CC*WW; i += 256) {
        int c = i >> 7, w = i & 127;
        XS[c*132 + w] = xrow[(size_t)c*HH*WW + w];
    }
    for (int i = tid; i < 4096; i += 256) {
        int e = i >> 6, o = i & 63;
        WVS[i] = wv[o*CC + e];
    }
    if (tid < 64) BVS[tid] = bv[tid];
    {
        const float* qt = g_Qt + (size_t)(b*HH + h)*WW*QD;
        for (int i = tid; i < 1024; i += 256) QS2[i] = qt[i];
    }

    // Phase A thread map: lane-consecutive e for coalesced T1 loads
    const int lane = tid & 31;
    const int e    = ((tid >> 5) & 1) * 32 + lane;   // 0..63, contiguous per warp
    const int wp   = tid >> 6;                       // 0..3

    float gwr[8], swr[8];
    {
        const float* gw = g_GW + ((size_t)(b*HH + h)*CC + e)*QD;
        float4 a = *(const float4*)gw;
        float4 c4 = *(const float4*)(gw + 4);
        gwr[0]=a.x; gwr[1]=a.y; gwr[2]=a.z; gwr[3]=a.w;
        gwr[4]=c4.x; gwr[5]=c4.y; gwr[6]=c4.z; gwr[7]=c4.w;
        const float* swp = g_sW + (b*HH + h)*QD;
        float4 s0 = *(const float4*)swp;
        float4 s1 = *(const float4*)(swp + 4);
        swr[0]=s0.x; swr[1]=s0.y; swr[2]=s0.z; swr[3]=s0.w;
        swr[4]=s1.x; swr[5]=s1.y; swr[6]=s1.z; swr[7]=s1.w;
    }
    __syncthreads();

    // S[w]
    if (tid < 128) {
        const int w = tid;
        const float* sh = g_sH + ((size_t)b*WW + w)*QD;
        float s = NEGV;
        #pragma unroll
        for (int q = 0; q < 8; q++) s = fmaf(QS2[w*8 + q], sh[q] + swr[q], s);
        SS[w] = s;
    }

    // Phase A: stream T1, add GW.Q + NEG*x
    {
        const float* t1B = g_T1 + ((size_t)(b*HH + h)*WW)*CC;
        #pragma unroll 4
        for (int it = 0; it < 32; it++) {
            const int w = wp + it*4;
            float tv = t1B[(size_t)w*CC + e];
            float4 qa = *(const float4*)&QS2[w*8];
            float4 qb = *(const float4*)&QS2[w*8 + 4];
            float t = fmaf(NEGV, XS[e*132 + w], tv);
            t = fmaf(qa.x, gwr[0], t);
            t = fmaf(qa.y, gwr[1], t);
            t = fmaf(qa.z, gwr[2], t);
            t = fmaf(qa.w, gwr[3], t);
            t = fmaf(qb.x, gwr[4], t);
            t = fmaf(qb.y, gwr[5], t);
            t = fmaf(qb.z, gwr[6], t);
            t = fmaf(qb.w, gwr[7], t);
            TS[e*132 + w] = t;
        }
    }
    __syncthreads();

    // Phase B: 64x64x128 GEMM with packed f32x2
    typedef unsigned long long u64;
    const int og = tid >> 5, blane = tid & 31, w0 = blane * 4;
    u64 acc2[4][4];
    {
        float4 b0 = *(const float4*)&BVS[og*8];
        float4 b1 = *(const float4*)&BVS[og*8 + 4];
        float bo[8] = {b0.x,b0.y,b0.z,b0.w,b1.x,b1.y,b1.z,b1.w};
        float4 s4 = *(const float4*)&SS[w0];
        float sj[4] = {s4.x,s4.y,s4.z,s4.w};
        #pragma unroll
        for (int p = 0; p < 4; p++)
            #pragma unroll
            for (int j = 0; j < 4; j++)
                acc2[p][j] = pk2(bo[2*p]*sj[j], bo[2*p+1]*sj[j]);
    }
    {
        const float4* wrow = (const float4*)&WVS[og*8];   // +16 float4 per e
        const float4* trow = (const float4*)&TS[w0];      // +33 float4 per e
        #pragma unroll 4
        for (int c = 0; c < CC; c++) {
            union { float4 f4; u64 u2[2]; } wa, wb, tv;
            wa.f4 = wrow[c*16];
            wb.f4 = wrow[c*16 + 1];
            tv.f4 = trow[c*33];
            u64 t0 = pk2(tv.f4.x, tv.f4.x);
            u64 t1 = pk2(tv.f4.y, tv.f4.y);
            u64 t2 = pk2(tv.f4.z, tv.f4.z);
            u64 t3 = pk2(tv.f4.w, tv.f4.w);
            FMA2(acc2[0][0], wa.u2[0], t0, acc2[0][0]);
            FMA2(acc2[0][1], wa.u2[0], t1, acc2[0][1]);
            FMA2(acc2[0][2], wa.u2[0], t2, acc2[0][2]);
            FMA2(acc2[0][3], wa.u2[0], t3, acc2[0][3]);
            FMA2(acc2[1][0], wa.u2[1], t0, acc2[1][0]);
            FMA2(acc2[1][1], wa.u2[1], t1, acc2[1][1]);
            FMA2(acc2[1][2], wa.u2[1], t2, acc2[1][2]);
            FMA2(acc2[1][3], wa.u2[1], t3, acc2[1][3]);
            FMA2(acc2[2][0], wb.u2[0], t0, acc2[2][0]);
            FMA2(acc2[2][1], wb.u2[0], t1, acc2[2][1]);
            FMA2(acc2[2][2], wb.u2[0], t2, acc2[2][2]);
            FMA2(acc2[2][3], wb.u2[0], t3, acc2[2][3]);
            FMA2(acc2[3][0], wb.u2[1], t0, acc2[3][0]);
            FMA2(acc2[3][1], wb.u2[1], t1, acc2[3][1]);
            FMA2(acc2[3][2], wb.u2[1], t2, acc2[3][2]);
            FMA2(acc2[3][3], wb.u2[1], t3, acc2[3][3]);
        }
    }
    {
        const float g = gamma[0];
        #pragma unroll
        for (int p = 0; p < 4; p++) {
            float2 r0 = upk2(acc2[p][0]);
            float2 r1 = upk2(acc2[p][1]);
            float2 r2 = upk2(acc2[p][2]);
            float2 r3 = upk2(acc2[p][3]);
            const int o = og*8 + 2*p;
            float4 xa = *(const float4*)&XS[o*132 + w0];
            float4 ov;
            ov.x = fmaf(g, r0.x, xa.x);
            ov.y = fmaf(g, r1.x, xa.y);
            ov.z = fmaf(g, r2.x, xa.z);
            ov.w = fmaf(g, r3.x, xa.w);
            *(float4*)&out[((size_t)(b*CC + o)*HH + h)*WW + w0] = ov;
            float4 xb = *(const float4*)&XS[(o+1)*132 + w0];
            ov.x = fmaf(g, r0.y, xb.x);
            ov.y = fmaf(g, r1.y, xb.y);
            ov.z = fmaf(g, r2.y, xb.z);
            ov.w = fmaf(g, r3.y, xb.w);
            *(float4*)&out[((size_t)(b*CC + o + 1)*HH + h)*WW + w0] = ov;
        }
    }
}

// ---------------------------------------------------------------------------
extern "C" void kernel_launch(void* const* d_in, const int* in_sizes, int n_in,
                              void* d_out, int out_size)
{
    const float* x     = (const float*)d_in[0];
    const float* wq    = (const float*)d_in[1];
    const float* bq    = (const float*)d_in[2];
    const float* wk    = (const float*)d_in[3];
    const float* bk    = (const float*)d_in[4];
    const float* wv    = (const float*)d_in[5];
    const float* bv    = (const float*)d_in[6];
    const float* gamma = (const float*)d_in[7];
    float* out = (float*)d_out;

    (void)in_sizes; (void)n_in; (void)out_size;

    cudaFuncSetAttribute(cc_p1_kernel, cudaFuncAttributeMaxDynamicSharedMemorySize,
                         S1_FLOATS * (int)sizeof(float));
    cudaFuncSetAttribute(cc_p2_kernel, cudaFuncAttributeMaxDynamicSharedMemorySize,
                         S2_FLOATS * (int)sizeof(float));
    cudaFuncSetAttribute(cc_p3_kernel, cudaFuncAttributeMaxDynamicSharedMemorySize,
                         S3_FLOATS * (int)sizeof(float));

    cc_p1_kernel<<<dim3(HH, BB), 256, S1_FLOATS * sizeof(float)>>>(
        x, wq, bq, wk, bk);
    cc_p2_kernel<<<dim3(WW/8, BB), 256, S2_FLOATS * sizeof(float)>>>(x);
    cc_p3_kernel<<<dim3(HH, BB), 256, S3_FLOATS * sizeof(float)>>>(
        x, wv, bv, gamma, out);
}

// round 16
// speedup vs baseline: 1.0117x; 1.0117x over previous
#include <cuda_runtime.h>
#include <math.h>

#define BB 32
#define CC 64
#define HH 128
#define WW 128
#define QD 8
#define NEGV (-1e4f)

// scratch
__device__ float g_Qt[BB*HH*WW*QD];   // [b,h,w,q] 16.8 MB
__device__ float g_Kt[BB*HH*WW*QD];   // [b,h,w,q] 16.8 MB
__device__ float g_GW[BB*HH*CC*QD];   // [b,h,e,q] 8.4 MB
__device__ float g_sW[BB*HH*QD];
__device__ float g_GH[BB*WW*CC*QD];   // [b,w,e,q] 8.4 MB
__device__ float g_sH[BB*WW*QD];

__device__ __forceinline__ float softplus_f(float v) {
    return fmaxf(v, 0.f) + log1pf(expf(-fabsf(v)));
}
typedef unsigned long long u64;
__device__ __forceinline__ u64 pk2(float lo, float hi) {
    u64 r;
    asm("mov.b64 %0, {%1, %2};" : "=l"(r) : "f"(lo), "f"(hi));
    return r;
}
__device__ __forceinline__ float2 upk2(u64 v) {
    float2 r;
    asm("mov.b64 {%0, %1}, %2;" : "=f"(r.x), "=f"(r.y) : "l"(v));
    return r;
}
#define FMA2(d, a, b, c) \
    asm("fma.rn.f32x2 %0, %1, %2, %3;" : "=l"(d) : "l"(a), "l"(b), "l"(c))

// ---------------------------------------------------------------------------
// P1: per (b,h). Q,K projections (softplus, FFMA2) + GW[e,q] = sum_w x[e,w]K[q,w],
// sW[q] = sum_w K[q,w] (warp-parallel). Writes Qt/Kt channels-last.
// ---------------------------------------------------------------------------
#define S1_FLOATS 10544

__global__ __launch_bounds__(256) void cc_p1_kernel(
    const float* __restrict__ x,
    const float* __restrict__ wq, const float* __restrict__ bq,
    const float* __restrict__ wk, const float* __restrict__ bk)
{
    extern __shared__ float sm[];
    float* XS  = sm;
    float* WQT = sm + 8448;   // [c*8+o]
    float* WKT = sm + 8960;
    float* BQS = sm + 9472;
    float* BKS = sm + 9480;
    float* KS  = sm + 9488;   // [q*132+w]

    const int b = blockIdx.y, h = blockIdx.x, tid = threadIdx.x;

    const float* xrow = x + ((size_t)(b*CC)*HH + h)*WW;
    for (int i = tid; i < 2048; i += 256) {          // float4 fill
        int c = i >> 5, w4 = (i & 31) * 4;
        *(float4*)&XS[c*132 + w4] =
            *(const float4*)&xrow[(size_t)c*HH*WW + w4];
    }
    for (int i = tid; i < 512; i += 256) {
        int c = i >> 3, o = i & 7;
        WQT[i] = wq[o*CC + c];
        WKT[i] = wk[o*CC + c];
    }
    if (tid < 8) { BQS[tid] = bq[tid]; BKS[tid] = bk[tid]; }
    __syncthreads();

    // projections with packed f32x2
    {
        const int w = tid & 127, half = tid >> 7;
        const float* WT = half ? WKT : WQT;
        const float* BT = half ? BKS : BQS;
        u64 acc2[4];
        #pragma unroll
        for (int i = 0; i < 4; i++) acc2[i] = pk2(BT[2*i], BT[2*i+1]);
        #pragma unroll 4
        for (int c = 0; c < CC; c++) {
            float xv = XS[c*132 + w];
            u64 xx = pk2(xv, xv);
            union { float4 f4; u64 u2[2]; } wa, wb;
            wa.f4 = *(const float4*)&WT[c*8];
            wb.f4 = *(const float4*)&WT[c*8 + 4];
            FMA2(acc2[0], wa.u2[0], xx, acc2[0]);
            FMA2(acc2[1], wa.u2[1], xx, acc2[1]);
            FMA2(acc2[2], wb.u2[0], xx, acc2[2]);
            FMA2(acc2[3], wb.u2[1], xx, acc2[3]);
        }
        float acc[8];
        #pragma unroll
        for (int i = 0; i < 4; i++) {
            float2 r = upk2(acc2[i]);
            acc[2*i]     = softplus_f(r.x);
            acc[2*i + 1] = softplus_f(r.y);
        }
        float* dst = (half ? g_Kt : g_Qt) + ((size_t)(b*HH + h)*WW + w)*QD;
        *(float4*)dst       = make_float4(acc[0], acc[1], acc[2], acc[3]);
        *(float4*)(dst + 4) = make_float4(acc[4], acc[5], acc[6], acc[7]);
        if (half) {
            #pragma unroll
            for (int o = 0; o < 8; o++) KS[o*132 + w] = acc[o];
        }
    }
    __syncthreads();

    // GW
    {
        const int e = tid >> 2, q0 = tid & 3, q1 = q0 + 4;
        float a0 = 0.f, a1 = 0.f;
        #pragma unroll 8
        for (int ww = 0; ww < WW; ww += 4) {
            float4 xv = *(const float4*)&XS[e*132 + ww];
            float4 k0 = *(const float4*)&KS[q0*132 + ww];
            float4 k1 = *(const float4*)&KS[q1*132 + ww];
            a0 = fmaf(xv.x,k0.x, fmaf(xv.y,k0.y, fmaf(xv.z,k0.z, fmaf(xv.w,k0.w, a0))));
            a1 = fmaf(xv.x,k1.x, fmaf(xv.y,k1.y, fmaf(xv.z,k1.z, fmaf(xv.w,k1.w, a1))));
        }
        float* gw = g_GW + ((size_t)(b*HH + h)*CC + e)*QD;
        gw[q0] = a0;
        gw[q1] = a1;
    }
    // sW: warp q = tid>>5, lanes partial-sum then butterfly reduce
    {
        const int q = tid >> 5, lane = tid & 31;
        float s = KS[q*132 + lane] + KS[q*132 + lane + 32]
                + KS[q*132 + lane + 64] + KS[q*132 + lane + 96];
        #pragma unroll
        for (int off = 16; off > 0; off >>= 1)
            s += __shfl_xor_sync(0xffffffffu, s, off);
        if (lane == 0) g_sW[(b*HH + h)*QD + q] = s;
    }
}

// ---------------------------------------------------------------------------
// P2: per (b, 8-wide w tile, 32-wide e half). GH[e,q;b,w] = sum_k x[e,k,w]K[q,k,w].
// grid (32, BB): blockIdx.x = wt(0..15) | ehalf<<4     (R11 version, unchanged)
// ---------------------------------------------------------------------------
#define S2_FLOATS 5120

__global__ __launch_bounds__(256) void cc_p2_kernel(const float* __restrict__ x)
{
    extern __shared__ float sm[];
    float* XS2 = sm;
    float* KS2 = sm + 4096;

    const int b = blockIdx.y;
    const int wt0 = (blockIdx.x & 15) * 8;
    const int e0  = (blockIdx.x >> 4) * 32;
    const int tid = threadIdx.x;
    const int eg = tid >> 5, wl = (tid >> 2) & 7, qp = tid & 3;

    float acc0[4], acc1[4];
    #pragma unroll
    for (int i = 0; i < 4; i++) { acc0[i] = 0.f; acc1[i] = 0.f; }
    float sa0 = 0.f, sa1 = 0.f;

    for (int k0 = 0; k0 < HH; k0 += 16) {
        for (int i = tid; i < 1024; i += 256) {     // XS2 fill (float4 units)
            int e = i >> 5, kk = (i >> 1) & 15, j = i & 1;
            *(float4*)&XS2[e*128 + kk*8 + j*4] =
                *(const float4*)(x + ((size_t)(b*CC + e0 + e)*HH + k0 + kk)*WW + wt0 + j*4);
        }
        for (int i = tid; i < 1024; i += 256) {     // KS2 fill
            int kk = i >> 6, ww = (i >> 3) & 7, q = i & 7;
            KS2[kk*64 + q*8 + ww] =
                g_Kt[((size_t)(b*HH + k0 + kk)*WW + wt0 + ww)*QD + q];
        }
        __syncthreads();
        #pragma unroll
        for (int kk = 0; kk < 16; kk++) {
            float kv0 = KS2[kk*64 + qp*8 + wl];
            float kv1 = KS2[kk*64 + (qp+4)*8 + wl];
            sa0 += kv0; sa1 += kv1;
            #pragma unroll
            for (int e2 = 0; e2 < 4; e2++) {
                float xv = XS2[(eg*4 + e2)*128 + kk*8 + wl];
                acc0[e2] = fmaf(xv, kv0, acc0[e2]);
                acc1[e2] = fmaf(xv, kv1, acc1[e2]);
            }
        }
        __syncthreads();
    }
    #pragma unroll
    for (int e2 = 0; e2 < 4; e2++) {
        float* gh = g_GH + ((size_t)(b*WW + wt0 + wl)*CC + e0 + eg*4 + e2)*QD;
        gh[qp]     = acc0[e2];
        gh[qp + 4] = acc1[e2];
    }
    if (eg == 0 && e0 == 0) {
        g_sH[(b*WW + wt0 + wl)*QD + qp]     = sa0;
        g_sH[(b*WW + wt0 + wl)*QD + qp + 4] = sa1;
    }
}

// ---------------------------------------------------------------------------
// P3: per (b, h-pair {h, h+64}). Each GH load feeds BOTH h rows.
//  Phase A: T_h[e,w] = sum_q Q_h[q,w](GH[e,q;b,w]+GW[e,q;b,h]) + NEG*x_h[e,w]
//  Phase B (x2): out[c,w] = gamma*( sum_e wvT[e][c]*T[e,w] + bv[c]*S[w] ) + x
// smem: XS0@0:8448 XS1@8448 TS0@16896 TS1@25344 WVS@33792:4096 BVS@37888:64
//       QS0@37952:1024 QS1@38976:1024 SS0@40000:128 SS1@40128:128
//   -> 40256 floats = 161024 B  (1 CTA/SM)
// ---------------------------------------------------------------------------
#define S3_FLOATS 40256

__global__ __launch_bounds__(256, 1) void cc_p3_kernel(
    const float* __restrict__ x,
    const float* __restrict__ wv, const float* __restrict__ bv,
    const float* __restrict__ gamma, float* __restrict__ out)
{
    extern __shared__ float sm[];
    float* XS0 = sm;            // [e*132+w]
    float* XS1 = sm + 8448;
    float* TS0 = sm + 16896;    // [e*132+w]
    float* TS1 = sm + 25344;
    float* WVS = sm + 33792;    // wv transposed: [e*64+o]
    float* BVS = sm + 37888;
    float* QS0 = sm + 37952;    // [w*8+q]
    float* QS1 = sm + 38976;
    float* SS0 = sm + 40000;
    float* SS1 = sm + 40128;

    const int b = blockIdx.y, h0 = blockIdx.x, h1 = h0 + 64, tid = threadIdx.x;

    const float* xb = x + (size_t)(b*CC)*HH*WW;
    for (int i = tid; i < 2048; i += 256) {
        int c = i >> 5, w4 = (i & 31) * 4;
        *(float4*)&XS0[c*132 + w4] =
            *(const float4*)&xb[((size_t)c*HH + h0)*WW + w4];
        *(float4*)&XS1[c*132 + w4] =
            *(const float4*)&xb[((size_t)c*HH + h1)*WW + w4];
    }
    for (int i = tid; i < 4096; i += 256) {
        int e = i >> 6, o = i & 63;
        WVS[i] = wv[o*CC + e];
    }
    if (tid < 64) BVS[tid] = bv[tid];
    {
        const float* qt0 = g_Qt + (size_t)(b*HH + h0)*WW*QD;
        const float* qt1 = g_Qt + (size_t)(b*HH + h1)*WW*QD;
        for (int i = tid; i < 1024; i += 256) {
            QS0[i] = qt0[i];
            QS1[i] = qt1[i];
        }
    }

    // Phase A thread map: lane-consecutive e for coalesced GH loads
    const int lane = tid & 31;
    const int e    = ((tid >> 5) & 1) * 32 + lane;   // 0..63, contiguous per warp
    const int wp   = tid >> 6;                       // 0..3

    float gw0[8], gw1[8], sw0[8], sw1[8];
    {
        const float* g0p = g_GW + ((size_t)(b*HH + h0)*CC + e)*QD;
        const float* g1p = g_GW + ((size_t)(b*HH + h1)*CC + e)*QD;
        float4 a0 = *(const float4*)g0p;
        float4 a1 = *(const float4*)(g0p + 4);
        gw0[0]=a0.x; gw0[1]=a0.y; gw0[2]=a0.z; gw0[3]=a0.w;
        gw0[4]=a1.x; gw0[5]=a1.y; gw0[6]=a1.z; gw0[7]=a1.w;
        float4 b0 = *(const float4*)g1p;
        float4 b1 = *(const float4*)(g1p + 4);
        gw1[0]=b0.x; gw1[1]=b0.y; gw1[2]=b0.z; gw1[3]=b0.w;
        gw1[4]=b1.x; gw1[5]=b1.y; gw1[6]=b1.z; gw1[7]=b1.w;
        const float* s0p = g_sW + (b*HH + h0)*QD;
        const float* s1p = g_sW + (b*HH + h1)*QD;
        float4 s0a = *(const float4*)s0p;
        float4 s0b = *(const float4*)(s0p + 4);
        sw0[0]=s0a.x; sw0[1]=s0a.y; sw0[2]=s0a.z; sw0[3]=s0a.w;
        sw0[4]=s0b.x; sw0[5]=s0b.y; sw0[6]=s0b.z; sw0[7]=s0b.w;
        float4 s1a = *(const float4*)s1p;
        float4 s1b = *(const float4*)(s1p + 4);
        sw1[0]=s1a.x; sw1[1]=s1a.y; sw1[2]=s1a.z; sw1[3]=s1a.w;
        sw1[4]=s1b.x; sw1[5]=s1b.y; sw1[6]=s1b.z; sw1[7]=s1b.w;
    }
    __syncthreads();

    // S[w] for both h
    if (tid < 128) {
        const int w = tid;
        const float* sh = g_sH + ((size_t)b*WW + w)*QD;
        float s0 = NEGV, s1 = NEGV;
        #pragma unroll
        for (int q = 0; q < 8; q++) {
            float shv = sh[q];
            s0 = fmaf(QS0[w*8 + q], shv + sw0[q], s0);
            s1 = fmaf(QS1[w*8 + q], shv + sw1[q], s1);
        }
        SS0[w] = s0;
        SS1[w] = s1;
    }

    // Phase A: each GH float4 pair serves both h rows
    {
        const float* ghB = g_GH + (size_t)b*WW*CC*QD;
        #pragma unroll 2
        for (int it = 0; it < 32; it++) {
            const int w = wp + it*4;
            const float4* gp = (const float4*)(ghB + ((size_t)w*CC + e)*QD);
            float4 g0 = gp[0];
            float4 g1 = gp[1];
            {
                float4 qa = *(const float4*)&QS0[w*8];
                float4 qb = *(const float4*)&QS0[w*8 + 4];
                float t = NEGV * XS0[e*132 + w];
                t = fmaf(qa.x, g0.x + gw0[0], t);
                t = fmaf(qa.y, g0.y + gw0[1], t);
                t = fmaf(qa.z, g0.z + gw0[2], t);
                t = fmaf(qa.w, g0.w + gw0[3], t);
                t = fmaf(qb.x, g1.x + gw0[4], t);
                t = fmaf(qb.y, g1.y + gw0[5], t);
                t = fmaf(qb.z, g1.z + gw0[6], t);
                t = fmaf(qb.w, g1.w + gw0[7], t);
                TS0[e*132 + w] = t;
            }
            {
                float4 qa = *(const float4*)&QS1[w*8];
                float4 qb = *(const float4*)&QS1[w*8 + 4];
                float t = NEGV * XS1[e*132 + w];
                t = fmaf(qa.x, g0.x + gw1[0], t);
                t = fmaf(qa.y, g0.y + gw1[1], t);
                t = fmaf(qa.z, g0.z + gw1[2], t);
                t = fmaf(qa.w, g0.w + gw1[3], t);
                t = fmaf(qb.x, g1.x + gw1[4], t);
                t = fmaf(qb.y, g1.y + gw1[5], t);
                t = fmaf(qb.z, g1.z + gw1[6], t);
                t = fmaf(qb.w, g1.w + gw1[7], t);
                TS1[e*132 + w] = t;
            }
        }
    }
    __syncthreads();

    // Phase B twice: 64x64x128 GEMM with packed f32x2
    const int og = tid >> 5, blane = tid & 31, w0 = blane * 4;
    #pragma unroll 1
    for (int hs = 0; hs < 2; hs++) {
        const float* TSp = hs ? TS1 : TS0;
        const float* SSp = hs ? SS1 : SS0;
        const float* XSp = hs ? XS1 : XS0;
        const int h = hs ? h1 : h0;

        u64 acc2[4][4];
        {
            float4 b0 = *(const float4*)&BVS[og*8];
            float4 b1 = *(const float4*)&BVS[og*8 + 4];
            float bo[8] = {b0.x,b0.y,b0.z,b0.w,b1.x,b1.y,b1.z,b1.w};
            float4 s4 = *(const float4*)&SSp[w0];
            float sj[4] = {s4.x,s4.y,s4.z,s4.w};
            #pragma unroll
            for (int p = 0; p < 4; p++)
                #pragma unroll
                for (int j = 0; j < 4; j++)
                    acc2[p][j] = pk2(bo[2*p]*sj[j], bo[2*p+1]*sj[j]);
        }
        {
            const float4* wrow = (const float4*)&WVS[og*8];   // +16 float4 per e
            const float4* trow = (const float4*)&TSp[w0];     // +33 float4 per e
            #pragma unroll 4
            for (int c = 0; c < CC; c++) {
                union { float4 f4; u64 u2[2]; } wa, wb, tv;
                wa.f4 = wrow[c*16];
                wb.f4 = wrow[c*16 + 1];
                tv.f4 = trow[c*33];
                u64 t0 = pk2(tv.f4.x, tv.f4.x);
                u64 t1 = pk2(tv.f4.y, tv.f4.y);
                u64 t2 = pk2(tv.f4.z, tv.f4.z);
                u64 t3 = pk2(tv.f4.w, tv.f4.w);
                FMA2(acc2[0][0], wa.u2[0], t0, acc2[0][0]);
                FMA2(acc2[0][1], wa.u2[0], t1, acc2[0][1]);
                FMA2(acc2[0][2], wa.u2[0], t2, acc2[0][2]);
                FMA2(acc2[0][3], wa.u2[0], t3, acc2[0][3]);
                FMA2(acc2[1][0], wa.u2[1], t0, acc2[1][0]);
                FMA2(acc2[1][1], wa.u2[1], t1, acc2[1][1]);
                FMA2(acc2[1][2], wa.u2[1], t2, acc2[1][2]);
                FMA2(acc2[1][3], wa.u2[1], t3, acc2[1][3]);
                FMA2(acc2[2][0], wb.u2[0], t0, acc2[2][0]);
                FMA2(acc2[2][1], wb.u2[0], t1, acc2[2][1]);
                FMA2(acc2[2][2], wb.u2[0], t2, acc2[2][2]);
                FMA2(acc2[2][3], wb.u2[0], t3, acc2[2][3]);
                FMA2(acc2[3][0], wb.u2[1], t0, acc2[3][0]);
                FMA2(acc2[3][1], wb.u2[1], t1, acc2[3][1]);
                FMA2(acc2[3][2], wb.u2[1], t2, acc2[3][2]);
                FMA2(acc2[3][3], wb.u2[1], t3, acc2[3][3]);
            }
        }
        {
            const float g = gamma[0];
            #pragma unroll
            for (int p = 0; p < 4; p++) {
                float2 r0 = upk2(acc2[p][0]);
                float2 r1 = upk2(acc2[p][1]);
                float2 r2 = upk2(acc2[p][2]);
                float2 r3 = upk2(acc2[p][3]);
                const int o = og*8 + 2*p;
                float4 xa = *(const float4*)&XSp[o*132 + w0];
                float4 ov;
                ov.x = fmaf(g, r0.x, xa.x);
                ov.y = fmaf(g, r1.x, xa.y);
                ov.z = fmaf(g, r2.x, xa.z);
                ov.w = fmaf(g, r3.x, xa.w);
                *(float4*)&out[((size_t)(b*CC + o)*HH + h)*WW + w0] = ov;
                float4 xb4 = *(const float4*)&XSp[(o+1)*132 + w0];
                ov.x = fmaf(g, r0.y, xb4.x);
                ov.y = fmaf(g, r1.y, xb4.y);
                ov.z = fmaf(g, r2.y, xb4.z);
                ov.w = fmaf(g, r3.y, xb4.w);
                *(float4*)&out[((size_t)(b*CC + o + 1)*HH + h)*WW + w0] = ov;
            }
        }
    }
}

// ---------------------------------------------------------------------------
extern "C" void kernel_launch(void* const* d_in, const int* in_sizes, int n_in,
                              void* d_out, int out_size)
{
    const float* x     = (const float*)d_in[0];
    const float* wq    = (const float*)d_in[1];
    const float* bq    = (const float*)d_in[2];
    const float* wk    = (const float*)d_in[3];
    const float* bk    = (const float*)d_in[4];
    const float* wv    = (const float*)d_in[5];
    const float* bv    = (const float*)d_in[6];
    const float* gamma = (const float*)d_in[7];
    float* out = (float*)d_out;

    (void)in_sizes; (void)n_in; (void)out_size;

    cudaFuncSetAttribute(cc_p1_kernel, cudaFuncAttributeMaxDynamicSharedMemorySize,
                         S1_FLOATS * (int)sizeof(float));
    cudaFuncSetAttribute(cc_p2_kernel, cudaFuncAttributeMaxDynamicSharedMemorySize,
                         S2_FLOATS * (int)sizeof(float));
    cudaFuncSetAttribute(cc_p3_kernel, cudaFuncAttributeMaxDynamicSharedMemorySize,
                         S3_FLOATS * (int)sizeof(float));

    cc_p1_kernel<<<dim3(HH, BB), 256, S1_FLOATS * sizeof(float)>>>(
        x, wq, bq, wk, bk);
    cc_p2_kernel<<<dim3(32, BB), 256, S2_FLOATS * sizeof(float)>>>(x);
    cc_p3_kernel<<<dim3(64, BB), 256, S3_FLOATS * sizeof(float)>>>(
        x, wv, bv, gamma, out);
}